// round 3
// baseline (speedup 1.0000x reference)
#include <cuda_runtime.h>
#include <math.h>

#define CC    96
#define HH    256
#define WWW   256
#define WS    16
#define NWIN  2048      // 8 * 16 * 16 windows
#define NREP  130       // representative positions per window under reflection
#define NREPP 144       // padded to 16*9 for clean register tiling
#define WPITCH 97       // padded W row pitch (float2) to avoid bank conflicts

__device__ float g_ar[NWIN * CC];   // 1 + real_att per (window, channel)
__device__ float g_ai[CC];          // 1 + imag_att per channel (constant over windows)

// ---------------------------------------------------------------------------
// Kernel A: attention scalars (4-way split dot products to cut serial chains).
// ---------------------------------------------------------------------------
__global__ void __launch_bounds__(384)
attn_kernel(const float* __restrict__ x,
            const float* __restrict__ w_real,
            const float* __restrict__ b_real,
            const float* __restrict__ b_imag,
            const float* __restrict__ car_w1, const float* __restrict__ car_b1,
            const float* __restrict__ car_w2, const float* __restrict__ car_b2,
            const float* __restrict__ cai_w1, const float* __restrict__ cai_b1,
            const float* __restrict__ cai_w2, const float* __restrict__ cai_b2)
{
    __shared__ float cv[CC];
    __shared__ float part[CC][4];
    __shared__ float pool[CC];
    __shared__ float hpart[32][4];
    __shared__ float hid[32];
    int t = threadIdx.x;
    int win = blockIdx.x;
    bool is_real = (win < NWIN);

    if (is_real) {
        int b  = win >> 8;
        int h0 = ((win >> 4) & 15) * WS;
        int w0 = (win & 15) * WS;
        if (t < CC) cv[t] = x[(((size_t)b * CC + t) * HH + h0) * WWW + w0];
        __syncthreads();
        // pool = w_real @ cv / 16 + b_real   (4 threads per output)
        {
            int c = t >> 2, p = t & 3;
            const float* wrow = w_real + c * CC + p * 24;
            float s = 0.f;
            #pragma unroll
            for (int k = 0; k < 24; k++) s += wrow[k] * cv[p * 24 + k];
            part[c][p] = s;
        }
        __syncthreads();
        if (t < CC)
            pool[t] = (part[t][0] + part[t][1] + part[t][2] + part[t][3]) * (1.0f / 16.0f)
                      + b_real[t];
        __syncthreads();
    } else {
        if (t < CC) pool[t] = b_imag[t];
        __syncthreads();
    }

    const float* w1 = is_real ? car_w1 : cai_w1;
    const float* b1 = is_real ? car_b1 : cai_b1;
    const float* w2 = is_real ? car_w2 : cai_w2;
    const float* b2 = is_real ? car_b2 : cai_b2;

    if (t < 128) {
        int c = t >> 2, p = t & 3;
        const float* wrow = w1 + c * CC + p * 24;
        float s = 0.f;
        #pragma unroll
        for (int k = 0; k < 24; k++) s += wrow[k] * pool[p * 24 + k];
        hpart[c][p] = s;
    }
    __syncthreads();
    if (t < 32)
        hid[t] = fmaxf(hpart[t][0] + hpart[t][1] + hpart[t][2] + hpart[t][3] + b1[t], 0.f);
    __syncthreads();
    if (t < CC) {
        float s = b2[t];
        #pragma unroll
        for (int j = 0; j < 32; j++) s += w2[t * 32 + j] * hid[j];
        float a = 1.f + 1.f / (1.f + expf(-s));
        if (is_real) g_ar[win * CC + t] = a;
        else         g_ai[t] = a;
    }
}

// ---------------------------------------------------------------------------
// Kernel B: main. 512 threads, 1 window per CTA.
//   S[k][r] = (x[n]+x[rho(n)])/2 ; D[k][r] = (x[n]-x[rho(n)])/2   (interleaved)
//   E = W_r S ; O = W_i D  (fused dual GEMM, float2-interleaved operands)
//   out[n] = a_r*E + a_i*O (+16*a_r*b_r at origin) ; out[rho(n)] = a_r*E - a_i*O
// ---------------------------------------------------------------------------
__global__ void __launch_bounds__(512, 1)
main_kernel(const float* __restrict__ x,
            const float* __restrict__ w_real,
            const float* __restrict__ w_imag,
            const float* __restrict__ b_real,
            float* __restrict__ out)
{
    extern __shared__ float2 sm[];
    float2* W2 = sm;                    // [96][WPITCH]  (wr, wi)
    float2* SD = W2 + CC * WPITCH;      // [96][NREPP]   (s, d)

    int t   = threadIdx.x;
    int win = blockIdx.x;
    int b   = win >> 8;
    int h0  = ((win >> 4) & 15) * WS;
    int w0  = (win & 15) * WS;

    // load + interleave channel-mix matrices (coalesced global, conflict-free smem)
    for (int idx = t; idx < CC * CC; idx += 512) {
        int c = idx / CC, k = idx - c * CC;
        W2[c * WPITCH + k] = make_float2(w_real[idx], w_imag[idx]);
    }

    // build even/odd tile (interleaved)
    const float* xb = x + (size_t)b * CC * HH * WWW;
    for (int idx = t; idx < CC * NREPP; idx += 512) {
        int k = idx / NREPP;
        int r = idx - k * NREPP;
        float sv = 0.f, dv = 0.f;
        if (r < NREP) {
            int p, q;
            if (r < 112) { p = 1 + (r >> 4); q = r & 15; }
            else { int r2 = r - 112; p = (r2 >= 9) ? 8 : 0; q = (r2 >= 9) ? (r2 - 9) : r2; }
            int p2 = (WS - p) & 15, q2 = (WS - q) & 15;
            float va = xb[((size_t)k * HH + h0 + p ) * WWW + w0 + q ];
            float vb = xb[((size_t)k * HH + h0 + p2) * WWW + w0 + q2];
            sv = 0.5f * (va + vb);
            dv = 0.5f * (va - vb);
        }
        SD[k * NREPP + r] = make_float2(sv, dv);
    }
    __syncthreads();

    // register-tiled fused dual GEMM:
    //   j = t&15 -> 9 rep columns {j+16m}, i = t>>4 -> 3 channel rows {i, i+32, i+64}
    int j = t & 15;
    int i = t >> 4;

    float acc_e[3][9], acc_o[3][9];
    #pragma unroll
    for (int a = 0; a < 3; a++)
        #pragma unroll
        for (int m = 0; m < 9; m++) { acc_e[a][m] = 0.f; acc_o[a][m] = 0.f; }

    const float2* w0p = W2 + (i     ) * WPITCH;
    const float2* w1p = W2 + (i + 32) * WPITCH;
    const float2* w2p = W2 + (i + 64) * WPITCH;

    #pragma unroll 2
    for (int k = 0; k < CC; k++) {
        float2 w[3];
        w[0] = w0p[k]; w[1] = w1p[k]; w[2] = w2p[k];
        float2 sd[9];
        #pragma unroll
        for (int m = 0; m < 9; m++) sd[m] = SD[k * NREPP + j + 16 * m];
        #pragma unroll
        for (int a = 0; a < 3; a++)
            #pragma unroll
            for (int m = 0; m < 9; m++) {
                acc_e[a][m] += w[a].x * sd[m].x;
                acc_o[a][m] += w[a].y * sd[m].y;
            }
    }

    // epilogue: attention scalars + scatter to both halves (q-coalesced stores)
    float arv[3], aiv[3];
    #pragma unroll
    for (int a = 0; a < 3; a++) {
        int c = i + 32 * a;
        arv[a] = g_ar[win * CC + c];
        aiv[a] = g_ai[c];
    }

    float* ob = out + (size_t)b * CC * HH * WWW;
    #pragma unroll
    for (int a = 0; a < 3; a++) {
        int c = i + 32 * a;
        float bias0 = 16.f * arv[a] * b_real[c];
        size_t base = ((size_t)c * HH + h0) * WWW + w0;
        #pragma unroll
        for (int m = 0; m < 9; m++) {
            int r = j + 16 * m;
            if (r >= NREP) continue;
            int p, q;
            if (r < 112) { p = 1 + m; q = j; }
            else { int r2 = r - 112; p = (r2 >= 9) ? 8 : 0; q = (r2 >= 9) ? (r2 - 9) : r2; }
            int p2 = (WS - p) & 15, q2 = (WS - q) & 15;
            float e = acc_e[a][m], o = acc_o[a][m];
            float v1 = arv[a] * e + aiv[a] * o;
            if (p == 0 && q == 0) v1 += bias0;
            ob[base + (size_t)p * WWW + q] = v1;
            if (p != p2 || q != q2)
                ob[base + (size_t)p2 * WWW + q2] = arv[a] * e - aiv[a] * o;
        }
    }
}

// ---------------------------------------------------------------------------
extern "C" void kernel_launch(void* const* d_in, const int* in_sizes, int n_in,
                              void* d_out, int out_size)
{
    const float* x      = (const float*)d_in[0];
    const float* w_real = (const float*)d_in[1];
    const float* b_real = (const float*)d_in[2];
    const float* w_imag = (const float*)d_in[3];
    const float* b_imag = (const float*)d_in[4];
    const float* car_w1 = (const float*)d_in[5];
    const float* car_b1 = (const float*)d_in[6];
    const float* car_w2 = (const float*)d_in[7];
    const float* car_b2 = (const float*)d_in[8];
    const float* cai_w1 = (const float*)d_in[9];
    const float* cai_b1 = (const float*)d_in[10];
    const float* cai_w2 = (const float*)d_in[11];
    const float* cai_b2 = (const float*)d_in[12];
    float* out = (float*)d_out;

    const int SMEM_BYTES = (CC * WPITCH + CC * NREPP) * (int)sizeof(float2); // 185,088
    cudaFuncSetAttribute(main_kernel, cudaFuncAttributeMaxDynamicSharedMemorySize, SMEM_BYTES);

    attn_kernel<<<NWIN + 1, 384>>>(x, w_real, b_real, b_imag,
                                   car_w1, car_b1, car_w2, car_b2,
                                   cai_w1, cai_b1, cai_w2, cai_b2);
    main_kernel<<<NWIN, 512, SMEM_BYTES>>>(x, w_real, w_imag, b_real, out);
}

// round 6
// speedup vs baseline: 1.2577x; 1.2577x over previous
#include <cuda_runtime.h>
#include <cstdint>
#include <math.h>

#define CC    96
#define HH    256
#define WWL   256
#define NWIN  2048
#define NREP  130
#define NT    256
#define EPITCH 146

// dynamic smem layout (floats)
//   WrP : [6 mt][12 ks][32 lane][4]  = 9216
//   WiP : 9216
//   SP/DP : [18 nt][12 ks][32 lane] float2 = 13824 floats each
//   Es/Os (union with SP/DP): 96*EPITCH each = 14016
#define WRP_F 0
#define WIP_F 9216
#define SDP_F 18432
#define SMEM_FLOATS (18432 + 2 * 96 * EPITCH)    // 46464
#define SMEM_DYN (SMEM_FLOATS * 4)               // 185856 B

// ---------------------------------------------------------------------------
__device__ __forceinline__ uint32_t tf32r(float f) {
    uint32_t u;
    asm("cvt.rna.tf32.f32 %0, %1;" : "=r"(u) : "f"(f));
    return u;
}
__device__ __forceinline__ void mma8(float* d, const uint32_t* a, const uint32_t* b) {
    asm volatile(
        "mma.sync.aligned.m16n8k8.row.col.f32.tf32.tf32.f32 "
        "{%0,%1,%2,%3}, {%4,%5,%6,%7}, {%8,%9}, {%0,%1,%2,%3};"
        : "+f"(d[0]), "+f"(d[1]), "+f"(d[2]), "+f"(d[3])
        : "r"(a[0]), "r"(a[1]), "r"(a[2]), "r"(a[3]), "r"(b[0]), "r"(b[1]));
}
__device__ __forceinline__ void decode_rq(int r, int& p, int& q) {
    if (r < 112) { p = 1 + (r >> 4); q = r & 15; }
    else { int r2 = r - 112; if (r2 < 9) { p = 0; q = r2; } else { p = 8; q = r2 - 9; } }
}

// ---------------------------------------------------------------------------
__global__ void __launch_bounds__(NT)
fused_kernel(const float* __restrict__ x,
             const float* __restrict__ w_real, const float* __restrict__ b_real,
             const float* __restrict__ w_imag, const float* __restrict__ b_imag,
             const float* __restrict__ car_w1, const float* __restrict__ car_b1,
             const float* __restrict__ car_w2, const float* __restrict__ car_b2,
             const float* __restrict__ cai_w1, const float* __restrict__ cai_b1,
             const float* __restrict__ cai_w2, const float* __restrict__ cai_b2,
             float* __restrict__ out)
{
    extern __shared__ float smf[];
    float* WrP = smf + WRP_F;
    float* WiP = smf + WIP_F;
    float2* SP = (float2*)(smf + SDP_F);          // 6912 float2
    float2* DP = SP + 6912;
    float* Es  = smf + SDP_F;                     // union (S/D dead by then)
    float* Os  = Es + 96 * EPITCH;

    __shared__ float s_cv[CC], s_pool[CC], s_hid[32], s_ar[CC], s_ai[CC];
    __shared__ float s_part[CC][2], s_hpart[32][2];

    const int t    = threadIdx.x;
    const int wid  = t >> 5;
    const int lane = t & 31;
    const int g    = lane >> 2;     // fragment group (row within tile)
    const int fid  = lane & 3;      // fragment thread-in-group (col within tile)

    const int win = blockIdx.x;
    const int b  = win >> 8;
    const int h0 = ((win >> 4) & 15) << 4;
    const int w0 = (win & 15) << 4;
    const float* xb = x + (size_t)b * CC * HH * WWL;

    // ---- W matrices -> fragment-permuted tf32 A-tiles ----
    // WP[mt][ks][lane][j]; frag j: row = 16*mt + g + 8*(j&1), col = 8*ks + fid + 4*(j>>1)
    for (int idx = t; idx < 9216; idx += NT) {
        int mt = idx / 1536;
        int rem = idx - mt * 1536;
        int ks = rem >> 7;
        int l  = (rem >> 2) & 31;
        int j  = rem & 3;
        int row = 16 * mt + (l >> 2) + 8 * (j & 1);
        int col = 8 * ks + (l & 3) + 4 * (j >> 1);
        WrP[idx] = __uint_as_float(tf32r(w_real[row * CC + col]));
        WiP[idx] = __uint_as_float(tf32r(w_imag[row * CC + col]));
    }

    // ---- build S/D B-tiles in fragment order ----
    // SP[nt][ks][lane] = (S[8ks+fid][8nt+g], S[8ks+fid+4][8nt+g])
    for (int idx = t; idx < 6912; idx += NT) {
        int l  = idx & 31;
        int ks = (idx >> 5) % 12;
        int nt = idx / 384;
        int r  = 8 * nt + (l >> 2);
        int k1 = 8 * ks + (l & 3);
        int k2 = k1 + 4;
        float2 sv = make_float2(0.f, 0.f), dv = make_float2(0.f, 0.f);
        if (r < NREP) {
            int p, q; decode_rq(r, p, q);
            int p2 = (16 - p) & 15, q2 = (16 - q) & 15;
            size_t o1 = ((size_t)(h0 + p)) * WWL + w0 + q;
            size_t o2 = ((size_t)(h0 + p2)) * WWL + w0 + q2;
            const float* x1 = xb + (size_t)k1 * HH * WWL;
            const float* x2 = xb + (size_t)k2 * HH * WWL;
            float a1 = x1[o1], b1v = x1[o2];
            float a2 = x2[o1], b2v = x2[o2];
            sv.x = __uint_as_float(tf32r(0.5f * (a1 + b1v)));
            sv.y = __uint_as_float(tf32r(0.5f * (a2 + b2v)));
            dv.x = __uint_as_float(tf32r(0.5f * (a1 - b1v)));
            dv.y = __uint_as_float(tf32r(0.5f * (a2 - b2v)));
        }
        SP[idx] = sv;
        DP[idx] = dv;
    }
    if (t < CC) s_cv[t] = xb[((size_t)t * HH + h0) * WWL + w0];
    __syncthreads();

    // ---- attention (2-way split dots) ----
    if (t < 192) {                       // real pool: w_real @ cv / 16 + b_real
        int c = t >> 1, p = t & 1;
        const float* wr = w_real + c * CC + p * 48;
        float s = 0.f;
        #pragma unroll 8
        for (int k = 0; k < 48; k++) s += wr[k] * s_cv[p * 48 + k];
        s_part[c][p] = s;
    }
    __syncthreads();
    if (t < CC) s_pool[t] = (s_part[t][0] + s_part[t][1]) * (1.f / 16.f) + b_real[t];
    __syncthreads();
    if (t < 64) {                        // real hidden
        int c = t >> 1, p = t & 1;
        const float* w1 = car_w1 + c * CC + p * 48;
        float s = 0.f;
        #pragma unroll 8
        for (int k = 0; k < 48; k++) s += w1[k] * s_pool[p * 48 + k];
        s_hpart[c][p] = s;
    } else if (t >= 128 && t < 192) {    // imag hidden (pool == b_imag exactly)
        int c = (t - 128) >> 1, p = t & 1;
        const float* w1 = cai_w1 + c * CC + p * 48;
        float s = 0.f;
        #pragma unroll 8
        for (int k = 0; k < 48; k++) s += w1[k] * b_imag[p * 48 + k];
        s_part[c][p] = s;                // reuse s_part rows 0..31 for imag hidden
    }
    __syncthreads();
    if (t < 32) s_hid[t] = fmaxf(s_hpart[t][0] + s_hpart[t][1] + car_b1[t], 0.f);
    else if (t >= 128 && t < 160) {
        int c = t - 128;
        s_part[c][0] = fmaxf(s_part[c][0] + s_part[c][1] + cai_b1[c], 0.f);  // imag hid
    }
    __syncthreads();
    if (t < CC) {
        float s = car_b2[t];
        const float* w2 = car_w2 + t * 32;
        #pragma unroll
        for (int j = 0; j < 32; j++) s += w2[j] * s_hid[j];
        s_ar[t] = 1.f + 1.f / (1.f + expf(-s));
    } else if (t >= 128 && t < 128 + CC) {
        int c = t - 128;
        float s = cai_b2[c];
        const float* w2 = cai_w2 + c * 32;
        #pragma unroll
        for (int j = 0; j < 32; j++) s += w2[j] * s_part[j][0];
        s_ai[c] = 1.f + 1.f / (1.f + expf(-s));
    }

    // ---- warp-level tf32 MMA: warps 0-3 -> E = Wr*S, warps 4-7 -> O = Wi*D ----
    const bool isO = wid >= 4;
    const int wg = wid & 3;
    const int wm = wg & 1;               // m half (48 rows)
    const int wn = wg >> 1;              // n half (72 cols = 9 n8 tiles)
    const uint4*  AP = (const uint4*)(isO ? WiP : WrP);
    const float2* BP = isO ? DP : SP;

    float acc[3][9][4];
    #pragma unroll
    for (int mt = 0; mt < 3; mt++)
        #pragma unroll
        for (int nt = 0; nt < 9; nt++)
            #pragma unroll
            for (int u = 0; u < 4; u++) acc[mt][nt][u] = 0.f;

    #pragma unroll
    for (int ks = 0; ks < 12; ks++) {
        uint4 afr[3];
        #pragma unroll
        for (int mt = 0; mt < 3; mt++)
            afr[mt] = AP[((wm * 3 + mt) * 12 + ks) * 32 + lane];
        uint32_t bfr[9][2];
        #pragma unroll
        for (int nt = 0; nt < 9; nt++) {
            float2 v = BP[((wn * 9 + nt) * 12 + ks) * 32 + lane];
            bfr[nt][0] = __float_as_uint(v.x);
            bfr[nt][1] = __float_as_uint(v.y);
        }
        #pragma unroll
        for (int mt = 0; mt < 3; mt++)
            #pragma unroll
            for (int nt = 0; nt < 9; nt++)
                mma8(acc[mt][nt], (const uint32_t*)&afr[mt], bfr[nt]);
    }
    __syncthreads();    // all warps done with S/D -> safe to overwrite with staging

    // ---- stage accumulators to smem ----
    {
        float* ST = isO ? Os : Es;
        #pragma unroll
        for (int mt = 0; mt < 3; mt++) {
            int mbase = 16 * (wm * 3 + mt);
            #pragma unroll
            for (int nt = 0; nt < 9; nt++) {
                int col = 8 * (wn * 9 + nt) + fid * 2;
                float* r1 = ST + (mbase + g) * EPITCH + col;
                float* r2 = ST + (mbase + g + 8) * EPITCH + col;
                *(float2*)r1 = make_float2(acc[mt][nt][0], acc[mt][nt][1]);
                *(float2*)r2 = make_float2(acc[mt][nt][2], acc[mt][nt][3]);
            }
        }
    }
    __syncthreads();

    // ---- recombine + coalesced scatter ----
    {
        int j = t & 15, i = t >> 4;
        float* ob = out + (size_t)b * CC * HH * WWL;
        #pragma unroll
        for (int a = 0; a < 6; a++) {
            int c = i + 16 * a;
            float ar = s_ar[c], ai = s_ai[c];
            float bias0 = 16.f * ar * b_real[c];
            size_t obase = ((size_t)c * HH + h0) * WWL + w0;
            const float* Er = Es + c * EPITCH;
            const float* Or = Os + c * EPITCH;
            #pragma unroll
            for (int m = 0; m < 9; m++) {
                int r = j + 16 * m;
                if (r >= NREP) continue;
                int p, q; decode_rq(r, p, q);
                int p2 = (16 - p) & 15, q2 = (16 - q) & 15;
                float e = Er[r], o = Or[r];
                float v1 = ar * e + ai * o;
                if (r == 112) v1 += bias0;                 // window origin (p=q=0)
                ob[obase + (size_t)p * WWL + q] = v1;
                if (p != p2 || q != q2)
                    ob[obase + (size_t)p2 * WWL + q2] = ar * e - ai * o;
            }
        }
    }
}

// ---------------------------------------------------------------------------
extern "C" void kernel_launch(void* const* d_in, const int* in_sizes, int n_in,
                              void* d_out, int out_size)
{
    const float* x      = (const float*)d_in[0];
    const float* w_real = (const float*)d_in[1];
    const float* b_real = (const float*)d_in[2];
    const float* w_imag = (const float*)d_in[3];
    const float* b_imag = (const float*)d_in[4];
    const float* car_w1 = (const float*)d_in[5];
    const float* car_b1 = (const float*)d_in[6];
    const float* car_w2 = (const float*)d_in[7];
    const float* car_b2 = (const float*)d_in[8];
    const float* cai_w1 = (const float*)d_in[9];
    const float* cai_b1 = (const float*)d_in[10];
    const float* cai_w2 = (const float*)d_in[11];
    const float* cai_b2 = (const float*)d_in[12];
    float* out = (float*)d_out;

    cudaFuncSetAttribute(fused_kernel, cudaFuncAttributeMaxDynamicSharedMemorySize, SMEM_DYN);
    fused_kernel<<<NWIN, NT, SMEM_DYN>>>(x, w_real, b_real, w_imag, b_imag,
                                         car_w1, car_b1, car_w2, car_b2,
                                         cai_w1, cai_b1, cai_w2, cai_b2, out);
}

// round 7
// speedup vs baseline: 1.5303x; 1.2167x over previous
#include <cuda_runtime.h>
#include <cstdint>
#include <math.h>

#define CC    96
#define HH    256
#define WWL   256
#define NWIN  2048
#define NREP  130
#define NT    512
#define NTILE 20          // padded n8 tiles (N=160)
#define EPITCH 144        // staging pitch: 144 % 32 == 16 -> conflict-free recombine reads

// dynamic smem layout (floats)
//   WrP : [6 mt][12 ks][32 lane][4] = 9216
//   WiP : 9216
//   SP/DP : [20 nt][12 ks][32 lane] float2 = 15360 floats each
//   Es/Os (union with SP/DP): 96*EPITCH = 13824 floats each
#define WRP_F 0
#define WIP_F 9216
#define SDP_F 18432
#define SMEM_FLOATS (18432 + 30720)     // 49152
#define SMEM_DYN (SMEM_FLOATS * 4)      // 196608 B

// ---------------------------------------------------------------------------
__device__ __forceinline__ uint32_t tf32r(float f) {
    uint32_t u;
    asm("cvt.rna.tf32.f32 %0, %1;" : "=r"(u) : "f"(f));
    return u;
}
__device__ __forceinline__ void mma8(float* d, const uint32_t* a, const uint32_t* b) {
    asm volatile(
        "mma.sync.aligned.m16n8k8.row.col.f32.tf32.tf32.f32 "
        "{%0,%1,%2,%3}, {%4,%5,%6,%7}, {%8,%9}, {%0,%1,%2,%3};"
        : "+f"(d[0]), "+f"(d[1]), "+f"(d[2]), "+f"(d[3])
        : "r"(a[0]), "r"(a[1]), "r"(a[2]), "r"(a[3]), "r"(b[0]), "r"(b[1]));
}
__device__ __forceinline__ void decode_rq(int r, int& p, int& q) {
    if (r < 112) { p = 1 + (r >> 4); q = r & 15; }
    else { int r2 = r - 112; if (r2 < 9) { p = 0; q = r2; } else { p = 8; q = r2 - 9; } }
}

// ---------------------------------------------------------------------------
__global__ void __launch_bounds__(NT, 1)
fused_kernel(const float* __restrict__ x,
             const float* __restrict__ w_real, const float* __restrict__ b_real,
             const float* __restrict__ w_imag, const float* __restrict__ b_imag,
             const float* __restrict__ car_w1, const float* __restrict__ car_b1,
             const float* __restrict__ car_w2, const float* __restrict__ car_b2,
             const float* __restrict__ cai_w1, const float* __restrict__ cai_b1,
             const float* __restrict__ cai_w2, const float* __restrict__ cai_b2,
             float* __restrict__ out)
{
    extern __shared__ float smf[];
    float* WrP = smf + WRP_F;
    float* WiP = smf + WIP_F;
    float2* SP = (float2*)(smf + SDP_F);          // 7680 float2
    float2* DP = SP + NTILE * 12 * 32;
    float* Es  = smf + SDP_F;                     // union (S/D dead by then)
    float* Os  = Es + CC * EPITCH;

    __shared__ float s_cv[CC], s_pool[CC], s_hid[32], s_ar[CC], s_ai[CC];
    __shared__ float s_part[CC][2], s_hpart[32][2];

    const int t    = threadIdx.x;
    const int wid  = t >> 5;
    const int lane = t & 31;
    const int g    = lane >> 2;
    const int fid  = lane & 3;

    const int win = blockIdx.x;
    const int b  = win >> 8;
    const int h0 = ((win >> 4) & 15) << 4;
    const int w0 = (win & 15) << 4;
    const float* xb = x + (size_t)b * CC * HH * WWL;

    // ---- W matrices -> fragment-permuted tf32 A-tiles ----
    for (int idx = t; idx < 9216; idx += NT) {
        int mt = idx / 1536;
        int rem = idx - mt * 1536;
        int ks = rem >> 7;
        int l  = (rem >> 2) & 31;
        int j  = rem & 3;
        int row = 16 * mt + (l >> 2) + 8 * (j & 1);
        int col = 8 * ks + (l & 3) + 4 * (j >> 1);
        WrP[idx] = __uint_as_float(tf32r(w_real[row * CC + col]));
        WiP[idx] = __uint_as_float(tf32r(w_imag[row * CC + col]));
    }

    // ---- build S/D B-tiles in fragment order ----
    for (int idx = t; idx < NTILE * 12 * 32; idx += NT) {
        int l  = idx & 31;
        int ks = (idx >> 5) % 12;
        int nt = idx / 384;
        int r  = 8 * nt + (l >> 2);
        int k1 = 8 * ks + (l & 3);
        int k2 = k1 + 4;
        float2 sv = make_float2(0.f, 0.f), dv = make_float2(0.f, 0.f);
        if (r < NREP) {
            int p, q; decode_rq(r, p, q);
            int p2 = (16 - p) & 15, q2 = (16 - q) & 15;
            size_t o1 = ((size_t)(h0 + p)) * WWL + w0 + q;
            size_t o2 = ((size_t)(h0 + p2)) * WWL + w0 + q2;
            const float* x1 = xb + (size_t)k1 * HH * WWL;
            const float* x2 = xb + (size_t)k2 * HH * WWL;
            float a1 = x1[o1], b1v = x1[o2];
            float a2 = x2[o1], b2v = x2[o2];
            sv.x = __uint_as_float(tf32r(0.5f * (a1 + b1v)));
            sv.y = __uint_as_float(tf32r(0.5f * (a2 + b2v)));
            dv.x = __uint_as_float(tf32r(0.5f * (a1 - b1v)));
            dv.y = __uint_as_float(tf32r(0.5f * (a2 - b2v)));
        }
        SP[idx] = sv;
        DP[idx] = dv;
    }
    if (t < CC) s_cv[t] = xb[((size_t)t * HH + h0) * WWL + w0];
    __syncthreads();

    // ---- attention (split dots; overlaps nothing but is short) ----
    if (t < 192) {
        int c = t >> 1, p = t & 1;
        const float* wr = w_real + c * CC + p * 48;
        float s = 0.f;
        #pragma unroll 8
        for (int k = 0; k < 48; k++) s += wr[k] * s_cv[p * 48 + k];
        s_part[c][p] = s;
    }
    __syncthreads();
    if (t < CC) s_pool[t] = (s_part[t][0] + s_part[t][1]) * (1.f / 16.f) + b_real[t];
    __syncthreads();
    if (t < 64) {
        int c = t >> 1, p = t & 1;
        const float* w1 = car_w1 + c * CC + p * 48;
        float s = 0.f;
        #pragma unroll 8
        for (int k = 0; k < 48; k++) s += w1[k] * s_pool[p * 48 + k];
        s_hpart[c][p] = s;
    } else if (t >= 128 && t < 192) {    // imag hidden (pool == b_imag exactly)
        int c = (t - 128) >> 1, p = t & 1;
        const float* w1 = cai_w1 + c * CC + p * 48;
        float s = 0.f;
        #pragma unroll 8
        for (int k = 0; k < 48; k++) s += w1[k] * b_imag[p * 48 + k];
        s_part[c][p] = s;
    }
    __syncthreads();
    if (t < 32) s_hid[t] = fmaxf(s_hpart[t][0] + s_hpart[t][1] + car_b1[t], 0.f);
    else if (t >= 128 && t < 160) {
        int c = t - 128;
        s_part[c][0] = fmaxf(s_part[c][0] + s_part[c][1] + cai_b1[c], 0.f);
    }
    __syncthreads();
    if (t < CC) {
        float s = car_b2[t];
        const float* w2 = car_w2 + t * 32;
        #pragma unroll
        for (int j = 0; j < 32; j++) s += w2[j] * s_hid[j];
        s_ar[t] = 1.f + 1.f / (1.f + expf(-s));
    } else if (t >= 128 && t < 128 + CC) {
        int c = t - 128;
        float s = cai_b2[c];
        const float* w2 = cai_w2 + c * 32;
        #pragma unroll
        for (int j = 0; j < 32; j++) s += w2[j] * s_part[j][0];
        s_ai[c] = 1.f + 1.f / (1.f + expf(-s));
    }

    // ---- warp-level tf32 MMA ----
    // 16 warps: 0-7 -> E = Wr*S, 8-15 -> O = Wi*D
    // per warp: m-half (wm: 3 mt) x n-quarter (wn: 5 nt of 20)
    const bool isO = wid >= 8;
    const int wg = wid & 7;
    const int wm = wg & 1;
    const int wn = wg >> 1;              // 0..3
    const uint4*  AP = (const uint4*)(isO ? WiP : WrP);
    const float2* BP = isO ? DP : SP;

    float acc[3][5][4];
    #pragma unroll
    for (int mt = 0; mt < 3; mt++)
        #pragma unroll
        for (int nt = 0; nt < 5; nt++)
            #pragma unroll
            for (int u = 0; u < 4; u++) acc[mt][nt][u] = 0.f;

    #pragma unroll
    for (int ks = 0; ks < 12; ks++) {
        uint4 afr[3];
        #pragma unroll
        for (int mt = 0; mt < 3; mt++)
            afr[mt] = AP[((wm * 3 + mt) * 12 + ks) * 32 + lane];
        uint32_t bfr[5][2];
        #pragma unroll
        for (int nt = 0; nt < 5; nt++) {
            float2 v = BP[((wn * 5 + nt) * 12 + ks) * 32 + lane];
            bfr[nt][0] = __float_as_uint(v.x);
            bfr[nt][1] = __float_as_uint(v.y);
        }
        #pragma unroll
        for (int mt = 0; mt < 3; mt++)
            #pragma unroll
            for (int nt = 0; nt < 5; nt++)
                mma8(acc[mt][nt], (const uint32_t*)&afr[mt], bfr[nt]);
    }
    __syncthreads();    // all warps done with S/D -> staging may overwrite

    // ---- stage accumulators to smem (only real columns: ntg <= 16) ----
    {
        float* ST = isO ? Os : Es;
        #pragma unroll
        for (int mt = 0; mt < 3; mt++) {
            int mbase = 16 * (wm * 3 + mt);
            #pragma unroll
            for (int nt = 0; nt < 5; nt++) {
                int ntg = wn * 5 + nt;
                if (ntg > 16) continue;
                int col = 8 * ntg + fid * 2;
                float* r1 = ST + (mbase + g) * EPITCH + col;
                float* r2 = ST + (mbase + g + 8) * EPITCH + col;
                *(float2*)r1 = make_float2(acc[mt][nt][0], acc[mt][nt][1]);
                *(float2*)r2 = make_float2(acc[mt][nt][2], acc[mt][nt][3]);
            }
        }
    }
    __syncthreads();

    // ---- recombine + coalesced scatter (512 threads: i=t>>4 in 0..31) ----
    {
        int j = t & 15, i = t >> 4;
        float* ob = out + (size_t)b * CC * HH * WWL;
        #pragma unroll
        for (int a = 0; a < 3; a++) {
            int c = i + 32 * a;
            float ar = s_ar[c], ai = s_ai[c];
            float bias0 = 16.f * ar * b_real[c];
            size_t obase = ((size_t)c * HH + h0) * WWL + w0;
            const float* Er = Es + c * EPITCH;
            const float* Or = Os + c * EPITCH;
            #pragma unroll
            for (int m = 0; m < 9; m++) {
                int r = j + 16 * m;
                if (r >= NREP) continue;
                int p, q; decode_rq(r, p, q);
                int p2 = (16 - p) & 15, q2 = (16 - q) & 15;
                float e = Er[r], o = Or[r];
                float v1 = ar * e + ai * o;
                if (r == 112) v1 += bias0;                 // window origin (p=q=0)
                ob[obase + (size_t)p * WWL + q] = v1;
                if (p != p2 || q != q2)
                    ob[obase + (size_t)p2 * WWL + q2] = ar * e - ai * o;
            }
        }
    }
}

// ---------------------------------------------------------------------------
extern "C" void kernel_launch(void* const* d_in, const int* in_sizes, int n_in,
                              void* d_out, int out_size)
{
    const float* x      = (const float*)d_in[0];
    const float* w_real = (const float*)d_in[1];
    const float* b_real = (const float*)d_in[2];
    const float* w_imag = (const float*)d_in[3];
    const float* b_imag = (const float*)d_in[4];
    const float* car_w1 = (const float*)d_in[5];
    const float* car_b1 = (const float*)d_in[6];
    const float* car_w2 = (const float*)d_in[7];
    const float* car_b2 = (const float*)d_in[8];
    const float* cai_w1 = (const float*)d_in[9];
    const float* cai_b1 = (const float*)d_in[10];
    const float* cai_w2 = (const float*)d_in[11];
    const float* cai_b2 = (const float*)d_in[12];
    float* out = (float*)d_out;

    cudaFuncSetAttribute(fused_kernel, cudaFuncAttributeMaxDynamicSharedMemorySize, SMEM_DYN);
    fused_kernel<<<NWIN, NT, SMEM_DYN>>>(x, w_real, b_real, w_imag, b_imag,
                                         car_w1, car_b1, car_w2, car_b2,
                                         cai_w1, cai_b1, cai_w2, cai_b2, out);
}

// round 12
// speedup vs baseline: 2.1613x; 1.4124x over previous
#include <cuda_runtime.h>
#include <cstdint>
#include <math.h>

#define CC    96
#define HH    256
#define WWL   256
#define NWIN  2048
#define NREP  130
#define NT    512
#define GRID  148
#define XPITCH 264        // window channel pitch (floats): mult of 8, %32==8
#define EPITCH 144        // staging pitch

// dynamic smem (floats):
//   WrP [6][12][32][4] = 9216 ; WiP = 9216
//   union: XW [96][264] = 25344  |  Es/Os [96][144] each = 27648
#define WRP_F 0
#define WIP_F 9216
#define XW_F  18432
#define ES_F  18432
#define OS_F  (18432 + CC * EPITCH)
#define SMEM_DYN ((18432 + 2 * CC * EPITCH) * 4)   // 184320 B

// ---------------------------------------------------------------------------
__device__ __forceinline__ uint32_t tf32r(float f) {
    uint32_t u;
    asm("cvt.rna.tf32.f32 %0, %1;" : "=r"(u) : "f"(f));
    return u;
}
__device__ __forceinline__ void mma8(float* d, const uint32_t* a, const uint32_t* b) {
    asm volatile(
        "mma.sync.aligned.m16n8k8.row.col.f32.tf32.tf32.f32 "
        "{%0,%1,%2,%3}, {%4,%5,%6,%7}, {%8,%9}, {%0,%1,%2,%3};"
        : "+f"(d[0]), "+f"(d[1]), "+f"(d[2]), "+f"(d[3])
        : "r"(a[0]), "r"(a[1]), "r"(a[2]), "r"(a[3]), "r"(b[0]), "r"(b[1]));
}
__device__ __forceinline__ void decode_rq(int r, int& p, int& q) {
    if (r < 112) { p = 1 + (r >> 4); q = r & 15; }
    else { int r2 = r - 112; if (r2 < 9) { p = 0; q = r2; } else { p = 8; q = r2 - 9; } }
}

// ---------------------------------------------------------------------------
__global__ void __launch_bounds__(NT, 1)
fused_kernel(const float* __restrict__ x,
             const float* __restrict__ w_real, const float* __restrict__ b_real,
             const float* __restrict__ w_imag, const float* __restrict__ b_imag,
             const float* __restrict__ car_w1, const float* __restrict__ car_b1,
             const float* __restrict__ car_w2, const float* __restrict__ car_b2,
             const float* __restrict__ cai_w1, const float* __restrict__ cai_b1,
             const float* __restrict__ cai_w2, const float* __restrict__ cai_b2,
             float* __restrict__ out)
{
    extern __shared__ float smf[];
    float* WrP = smf + WRP_F;
    float* WiP = smf + WIP_F;
    float* XW  = smf + XW_F;
    float* Es  = smf + ES_F;
    float* Os  = smf + OS_F;

    __shared__ float s_pool[CC], s_hid[32], s_ar[CC], s_ai[CC];
    __shared__ float s_part[CC][2], s_hpart[32][2];

    const int t    = threadIdx.x;
    const int wid  = t >> 5;
    const int lane = t & 31;
    const int g    = lane >> 2;
    const int fid  = lane & 3;

    // ---- one-time: W matrices -> fragment-permuted tf32 A-tiles ----
    for (int idx = t; idx < 9216; idx += NT) {
        int mt = idx / 1536;
        int rem = idx - mt * 1536;
        int ks = rem >> 7;
        int l  = (rem >> 2) & 31;
        int j  = rem & 3;
        int row = 16 * mt + (l >> 2) + 8 * (j & 1);
        int col = 8 * ks + (l & 3) + 4 * (j >> 1);
        WrP[idx] = __uint_as_float(tf32r(w_real[row * CC + col]));
        WiP[idx] = __uint_as_float(tf32r(w_imag[row * CC + col]));
    }

    // ---- one-time: imag attention (pool == b_imag exactly) ----
    if (t < 64) {
        int c = t >> 1, p = t & 1;
        const float* w1 = cai_w1 + c * CC + p * 48;
        float s = 0.f;
        #pragma unroll 8
        for (int k = 0; k < 48; k++) s += w1[k] * b_imag[p * 48 + k];
        s_hpart[c][p] = s;
    }
    __syncthreads();
    if (t < 32) s_hid[t] = fmaxf(s_hpart[t][0] + s_hpart[t][1] + cai_b1[t], 0.f);
    __syncthreads();
    if (t < CC) {
        float s = cai_b2[t];
        const float* w2 = cai_w2 + t * 32;
        #pragma unroll
        for (int j = 0; j < 32; j++) s += w2[j] * s_hid[j];
        s_ai[t] = 1.f + 1.f / (1.f + expf(-s));
    }

    // ---- per-warp MMA geometry + precomputed B positions ----
    const bool isO = wid >= 8;
    const int wg = wid & 7;
    const int wm = wg & 1;               // m half: 3 mt tiles
    const int wn = wg >> 1;              // n quarter: 5 nt tiles
    const uint4* AP = (const uint4*)(isO ? WiP : WrP);
    const float sgn = isO ? -0.5f : 0.5f;

    int paddr[5];
    #pragma unroll
    for (int nt = 0; nt < 5; nt++) {
        int r = 8 * (wn * 5 + nt) + g;
        int p, q; decode_rq(r, p, q);
        int p2 = (16 - p) & 15, q2 = (16 - q) & 15;
        paddr[nt] = (p * 16 + q) | ((p2 * 16 + q2) << 16);
    }

    // ================= persistent window loop =================
    for (int win = blockIdx.x; win < NWIN; win += GRID) {
        const int b  = win >> 8;
        const int h0 = ((win >> 4) & 15) << 4;
        const int w0 = (win & 15) << 4;
        const float* xb = x + (size_t)b * CC * HH * WWL;

        __syncthreads();   // previous iteration's Es/Os reads done; XW free

        // ---- stage raw window: coalesced float4 loads ----
        for (int idx = t; idx < CC * 64; idx += NT) {
            int k = idx >> 6, f = idx & 63;
            int p = f >> 2, qg = (f & 3) << 2;
            float4 v = *(const float4*)(xb + (size_t)k * (HH * WWL)
                                        + (size_t)(h0 + p) * WWL + w0 + qg);
            *(float4*)(XW + k * XPITCH + p * 16 + qg) = v;
        }
        __syncthreads();

        // ---- real attention (from window corner) ----
        if (t < 192) {
            int c = t >> 1, p = t & 1;
            const float* wr = w_real + c * CC + p * 48;
            float s = 0.f;
            #pragma unroll 8
            for (int k = 0; k < 48; k++) s += wr[k] * XW[(p * 48 + k) * XPITCH];
            s_part[c][p] = s;
        }
        __syncthreads();
        if (t < CC) s_pool[t] = (s_part[t][0] + s_part[t][1]) * (1.f / 16.f) + b_real[t];
        __syncthreads();
        if (t < 64) {
            int c = t >> 1, p = t & 1;
            const float* w1 = car_w1 + c * CC + p * 48;
            float s = 0.f;
            #pragma unroll 8
            for (int k = 0; k < 48; k++) s += w1[k] * s_pool[p * 48 + k];
            s_hpart[c][p] = s;
        }
        __syncthreads();
        if (t < 32) s_hid[t] = fmaxf(s_hpart[t][0] + s_hpart[t][1] + car_b1[t], 0.f);
        __syncthreads();
        if (t < CC) {
            float s = car_b2[t];
            const float* w2 = car_w2 + t * 32;
            #pragma unroll
            for (int j = 0; j < 32; j++) s += w2[j] * s_hid[j];
            s_ar[t] = 1.f + 1.f / (1.f + expf(-s));
        }
        // (s_ar visibility to all warps is ordered by the post-MMA barrier)

        // ---- MMA with on-the-fly even/odd B-fragments ----
        float acc[3][5][4];
        #pragma unroll
        for (int mt = 0; mt < 3; mt++)
            #pragma unroll
            for (int nt = 0; nt < 5; nt++)
                #pragma unroll
                for (int u = 0; u < 4; u++) acc[mt][nt][u] = 0.f;

        #pragma unroll
        for (int ks = 0; ks < 12; ks++) {
            uint4 afr[3];
            #pragma unroll
            for (int mt = 0; mt < 3; mt++)
                afr[mt] = AP[((wm * 3 + mt) * 12 + ks) * 32 + lane];

            const float* xk = XW + (8 * ks + fid) * XPITCH;
            uint32_t bfr[5][2];
            #pragma unroll
            for (int nt = 0; nt < 5; nt++) {
                int o1 = paddr[nt] & 0xFFFF, o2 = paddr[nt] >> 16;
                float a1 = xk[o1],            b1v = xk[o2];
                float a2 = xk[4 * XPITCH + o1], b2v = xk[4 * XPITCH + o2];
                bfr[nt][0] = tf32r(0.5f * a1 + sgn * b1v);
                bfr[nt][1] = tf32r(0.5f * a2 + sgn * b2v);
            }
            #pragma unroll
            for (int mt = 0; mt < 3; mt++)
                #pragma unroll
                for (int nt = 0; nt < 5; nt++)
                    mma8(acc[mt][nt], (const uint32_t*)&afr[mt], bfr[nt]);
        }
        __syncthreads();   // all MMA/attention reads of XW done -> staging may overwrite

        // ---- stage accumulators (real columns only: ntg <= 16) ----
        {
            float* ST = isO ? Os : Es;
            #pragma unroll
            for (int mt = 0; mt < 3; mt++) {
                int mbase = 16 * (wm * 3 + mt);
                #pragma unroll
                for (int nt = 0; nt < 5; nt++) {
                    int ntg = wn * 5 + nt;
                    if (ntg > 16) continue;
                    int col = 8 * ntg + fid * 2;
                    float* r1 = ST + (mbase + g) * EPITCH + col;
                    float* r2 = ST + (mbase + g + 8) * EPITCH + col;
                    *(float2*)r1 = make_float2(acc[mt][nt][0], acc[mt][nt][1]);
                    *(float2*)r2 = make_float2(acc[mt][nt][2], acc[mt][nt][3]);
                }
            }
        }
        __syncthreads();

        // ---- recombine + coalesced scatter ----
        {
            int j = t & 15, i = t >> 4;
            float* ob = out + (size_t)b * CC * HH * WWL;
            #pragma unroll
            for (int a = 0; a < 3; a++) {
                int c = i + 32 * a;
                float ar = s_ar[c], ai = s_ai[c];
                float bias0 = 16.f * ar * b_real[c];
                size_t obase = ((size_t)c * HH + h0) * WWL + w0;
                const float* Er = Es + c * EPITCH;
                const float* Or = Os + c * EPITCH;
                #pragma unroll
                for (int m = 0; m < 9; m++) {
                    int r = j + 16 * m;
                    if (r >= NREP) continue;
                    int p, q; decode_rq(r, p, q);
                    int p2 = (16 - p) & 15, q2 = (16 - q) & 15;
                    float e = Er[r], o = Or[r];
                    float v1 = ar * e + ai * o;
                    if (r == 112) v1 += bias0;                 // window origin (p=q=0)
                    ob[obase + (size_t)p * WWL + q] = v1;
                    if (p != p2 || q != q2)
                        ob[obase + (size_t)p2 * WWL + q2] = ar * e - ai * o;
                }
            }
        }
    }
}

// ---------------------------------------------------------------------------
extern "C" void kernel_launch(void* const* d_in, const int* in_sizes, int n_in,
                              void* d_out, int out_size)
{
    const float* x      = (const float*)d_in[0];
    const float* w_real = (const float*)d_in[1];
    const float* b_real = (const float*)d_in[2];
    const float* w_imag = (const float*)d_in[3];
    const float* b_imag = (const float*)d_in[4];
    const float* car_w1 = (const float*)d_in[5];
    const float* car_b1 = (const float*)d_in[6];
    const float* car_w2 = (const float*)d_in[7];
    const float* car_b2 = (const float*)d_in[8];
    const float* cai_w1 = (const float*)d_in[9];
    const float* cai_b1 = (const float*)d_in[10];
    const float* cai_w2 = (const float*)d_in[11];
    const float* cai_b2 = (const float*)d_in[12];
    float* out = (float*)d_out;

    cudaFuncSetAttribute(fused_kernel, cudaFuncAttributeMaxDynamicSharedMemorySize, SMEM_DYN);
    fused_kernel<<<GRID, NT, SMEM_DYN>>>(x, w_real, b_real, w_imag, b_imag,
                                         car_w1, car_b1, car_w2, car_b2,
                                         cai_w1, cai_b1, cai_w2, cai_b2, out);
}